// round 9
// baseline (speedup 1.0000x reference)
// NOTE (pitfall, R4): harness PTX target is sm_103 (no 'a') -> no tcgen05/TMEM.
// NOTE (pitfall, R3+R6): asm-volatile ldmatrix serializes vs MMA; plain C++ LDS
// that ptxas schedules wins. Fragment loads must stay compiler-visible.
#include <cuda_runtime.h>
#include <cuda_fp16.h>
#include <stdint.h>

#define H     128
#define CIN   64
#define NNODE 512
#define BATCH 2

// u32 (=half2) stride; 72 ≡ 8 (mod 32) -> LDS.64 fragment loads conflict-free
#define ESTRIDE 72

// smem layout (bytes)
#define OFF_ES   0
#define SZ_T     (128 * ESTRIDE * 4)             // 36864
#define OFF_W2   (OFF_ES + SZ_T)                 // 36864
#define OFF_W3   (OFF_W2 + SZ_T)                 // 73728
#define OFF_BC2  (OFF_W3 + SZ_T)                 // 110592
#define OFF_BC3  (OFF_BC2 + 512)
#define OFF_WO   (OFF_BC3 + 512)
#define SMEM_BYTES (OFF_WO + 512)                // 112128

// scratch: u[b,n,k] = (relu-MLP h2)[b,n,:] @ Wc1
__device__ float g_U[BATCH * NNODE * H];

// ---------------------------------------------------------------------------
// half2-column permutation: pair (h, h+4) within each 8-group becomes adjacent
__device__ __host__ __forceinline__ int slotf(int h) {
    return (h & ~7) | ((h & 3) << 1) | ((h >> 2) & 1);
}

__device__ __forceinline__ uint32_t pack2(float a, float b) {
    __half2 h = __floats2half2_rn(a, b);
    return *reinterpret_cast<uint32_t*>(&h);
}

__device__ __forceinline__ void mma_f16(float c[4], const uint32_t a[4],
                                        uint32_t b0, uint32_t b1) {
    asm("mma.sync.aligned.m16n8k16.row.col.f32.f16.f16.f32 "
        "{%0,%1,%2,%3}, {%4,%5,%6,%7}, {%8,%9}, {%0,%1,%2,%3};"
        : "+f"(c[0]), "+f"(c[1]), "+f"(c[2]), "+f"(c[3])
        : "r"(a[0]), "r"(a[1]), "r"(a[2]), "r"(a[3]), "r"(b0), "r"(b1));
}

// 128x128x128 fp16 GEMM; fragments via plain uint2 (LDS.64), permuted layout.
// A0/A1: &E[(m_base + mt*16 + qid) * 36 + tq] as uint2; B: &W[(n_base+qid)*36+tq]
__device__ __forceinline__ void gemm128h(const uint2* __restrict__ A0,
                                         const uint2* __restrict__ A1,
                                         const uint2* __restrict__ B,
                                         float acc[2][8][4]) {
#pragma unroll
    for (int k0 = 0; k0 < 8; k0++) {
        uint2 u00 = A0[k0 * 4];
        uint2 u01 = A0[k0 * 4 + 8 * 36];
        uint2 u10 = A1[k0 * 4];
        uint2 u11 = A1[k0 * 4 + 8 * 36];
        uint32_t a0[4] = {u00.x, u01.x, u00.y, u01.y};
        uint32_t a1[4] = {u10.x, u11.x, u10.y, u11.y};
#pragma unroll
        for (int nt = 0; nt < 8; nt++) {
            uint2 w = B[nt * (8 * 36) + k0 * 4];
            mma_f16(acc[0][nt], a0, w.x, w.y);
            mma_f16(acc[1][nt], a1, w.x, w.y);
        }
    }
}

// ---------------------------------------------------------------------------
// init: out[...] = bo   (stage2 epilogue uses RED.GLOBAL.ADD directly)
// ---------------------------------------------------------------------------
__global__ __launch_bounds__(256) void init_out_kernel(float* __restrict__ out,
                                                       const float* __restrict__ bo) {
    float v = bo[0];
    float4 vv = make_float4(v, v, v, v);
    int i = blockIdx.x * blockDim.x + threadIdx.x;
    ((float4*)out)[2 * i]     = vv;
    ((float4*)out)[2 * i + 1] = vv;
}

// ---------------------------------------------------------------------------
// stage 1: node MLP + u = h2 @ Wc1   (fp32 exact, tiny)
// ---------------------------------------------------------------------------
#define S1_NODES 4
__global__ __launch_bounds__(128) void stage1_kernel(
    const float* __restrict__ x,
    const float* __restrict__ Wa, const float* __restrict__ ba,
    const float* __restrict__ Wb, const float* __restrict__ bb,
    const float* __restrict__ Wc1) {
    __shared__ float xs[S1_NODES][CIN];
    __shared__ float h1s[S1_NODES][H + 4];
    __shared__ float h2s[S1_NODES][H + 4];
    int tid = threadIdx.x;
    int node0 = blockIdx.x * S1_NODES;

    for (int idx = tid; idx < S1_NODES * CIN; idx += 128)
        xs[idx / CIN][idx % CIN] = x[node0 * CIN + idx];
    __syncthreads();

    int k = tid;
    float acc[S1_NODES];
#pragma unroll
    for (int m = 0; m < S1_NODES; m++) acc[m] = ba[k];
#pragma unroll 8
    for (int c = 0; c < CIN; c++) {
        float w = Wa[c * H + k];
#pragma unroll
        for (int m = 0; m < S1_NODES; m++) acc[m] += xs[m][c] * w;
    }
#pragma unroll
    for (int m = 0; m < S1_NODES; m++) h1s[m][k] = fmaxf(acc[m], 0.f);
    __syncthreads();

#pragma unroll
    for (int m = 0; m < S1_NODES; m++) acc[m] = bb[k];
#pragma unroll 8
    for (int c = 0; c < H; c++) {
        float w = Wb[c * H + k];
#pragma unroll
        for (int m = 0; m < S1_NODES; m++) acc[m] += h1s[m][c] * w;
    }
#pragma unroll
    for (int m = 0; m < S1_NODES; m++) h2s[m][k] = fmaxf(acc[m], 0.f);
    __syncthreads();

#pragma unroll
    for (int m = 0; m < S1_NODES; m++) acc[m] = 0.f;
#pragma unroll 8
    for (int c = 0; c < H; c++) {
        float w = Wc1[c * H + k];
#pragma unroll
        for (int m = 0; m < S1_NODES; m++) acc[m] += h2s[m][c] * w;
    }
#pragma unroll
    for (int m = 0; m < S1_NODES; m++) g_U[(node0 + m) * H + k] = acc[m];
}

// ---------------------------------------------------------------------------
// stage 2: per-edge MLP via fp16 mma (fp32 accum), LDS.64 fragments,
//          2 CTAs / SM, 4 syncs/tile
// ---------------------------------------------------------------------------
__global__ __launch_bounds__(256, 2) void stage2_kernel(
    const float* __restrict__ bc1,
    const float* __restrict__ Wc2, const float* __restrict__ bc2,
    const float* __restrict__ Wc3, const float* __restrict__ bc3,
    const float* __restrict__ Wo,
    float* __restrict__ out, int ntiles) {
    extern __shared__ unsigned char smem[];
    uint32_t* Es  = (uint32_t*)(smem + OFF_ES);
    uint32_t* W2T = (uint32_t*)(smem + OFF_W2);
    uint32_t* W3T = (uint32_t*)(smem + OFF_W3);
    float* bc2s = (float*)(smem + OFF_BC2);
    float* bc3s = (float*)(smem + OFF_BC3);
    float* wos  = (float*)(smem + OFF_WO);

    int tid = threadIdx.x;

    // one-time: stage weights TRANSPOSED + column-permuted:
    //   W?T[n][slot(kp)] = (W[2kp][n], W[2kp+1][n])
    for (int idx = tid; idx < H * 64; idx += 256) {
        int n = idx >> 6, kp = idx & 63;
        int sl = n * ESTRIDE + slotf(kp);
        W2T[sl] = pack2(Wc2[(2 * kp) * H + n], Wc2[(2 * kp + 1) * H + n]);
        W3T[sl] = pack2(Wc3[(2 * kp) * H + n], Wc3[(2 * kp + 1) * H + n]);
    }
    if (tid < H) {
        bc2s[tid] = bc2[tid];
        bc3s[tid] = bc3[tid];
        wos[tid]  = Wo[tid];
    }

    // fill mapping: thread owns float cols 4cg..4cg+3 (= half2 cols 2cg, 2cg+1)
    int cg  = tid & 31;
    int rph = tid >> 5;
    int s0 = slotf(2 * cg);
    int s1 = slotf(2 * cg + 1);
    float4 bc1v = ((const float4*)bc1)[cg];
    __syncthreads();

    int warp = tid >> 5, lane = tid & 31;
    int wm = warp >> 1, wn = warp & 1;
    int m_base = wm * 32, n_base = wn * 64;
    int qid = lane >> 2, tq = lane & 3;
    int nb2 = wn * 32;   // n_base in half2 units

    // fragment base pointers (uint2 = LDS.64)
    const uint2* EA0 = (const uint2*)Es + (size_t)(m_base + qid) * 36 + tq;
    const uint2* EA1 = EA0 + 16 * 36;
    const uint2* WB2 = (const uint2*)W2T + (size_t)(n_base + qid) * 36 + tq;
    const uint2* WB3 = (const uint2*)W3T + (size_t)(n_base + qid) * 36 + tq;

    // E2 writeback bases (addresses fold to base + compile-time const per nt)
    int wb0 = (m_base + qid) * ESTRIDE + nb2 + 2 * tq;
    int wb1 = wb0 + 16 * ESTRIDE;

    for (int t = blockIdx.x; t < ntiles; t += gridDim.x) {
        int jt = t & 3;
        int i  = (t >> 2) & (NNODE - 1);
        int b  = t >> 11;
        int j0 = jt << 7;
        const float4* Ub4 = (const float4*)(g_U + (size_t)b * NNODE * H);

        // vcomb = bc1 - u_i (this thread's 4 columns)
        float4 ui = Ub4[i * 32 + cg];
        float4 vc = make_float4(bc1v.x - ui.x, bc1v.y - ui.y,
                                bc1v.z - ui.z, bc1v.w - ui.w);

        // E1[j,k] = ReLU(u_j + vc) -> permuted half2 in smem (16 rows/thread)
#pragma unroll 4
        for (int it = 0; it < 16; it++) {
            int jj = rph + 8 * it;
            float4 u = Ub4[(size_t)(j0 + jj) * 32 + cg];
            Es[jj * ESTRIDE + s0] = pack2(fmaxf(u.x + vc.x, 0.f),
                                          fmaxf(u.y + vc.y, 0.f));
            Es[jj * ESTRIDE + s1] = pack2(fmaxf(u.z + vc.z, 0.f),
                                          fmaxf(u.w + vc.w, 0.f));
        }
        __syncthreads();  // (A) E1 ready

        // GEMM1: Z2 = E1 @ Wc2
        float acc[2][8][4];
#pragma unroll
        for (int mt = 0; mt < 2; mt++)
#pragma unroll
            for (int nt = 0; nt < 8; nt++)
#pragma unroll
                for (int q = 0; q < 4; q++) acc[mt][nt][q] = 0.f;
        gemm128h(EA0, EA1, WB2, acc);
        __syncthreads();  // (B) E1 reads done

        // E2 = ReLU(Z2 + bc2) -> permuted half2 back into Es
#pragma unroll
        for (int mt = 0; mt < 2; mt++) {
            int base = (mt == 0) ? wb0 : wb1;
#pragma unroll
            for (int nt = 0; nt < 8; nt++) {
                int n = n_base + nt * 8 + 2 * tq;
                int C = ((nt & ~1) << 2) | (nt & 1);   // slot offset, compile-time
                Es[base + C] =
                    pack2(fmaxf(acc[mt][nt][0] + bc2s[n], 0.f),
                          fmaxf(acc[mt][nt][1] + bc2s[n + 1], 0.f));
                Es[base + 8 * ESTRIDE + C] =
                    pack2(fmaxf(acc[mt][nt][2] + bc2s[n], 0.f),
                          fmaxf(acc[mt][nt][3] + bc2s[n + 1], 0.f));
            }
        }
        __syncthreads();  // (C) E2 ready

        // GEMM2: Z3 = E2 @ Wc3
#pragma unroll
        for (int mt = 0; mt < 2; mt++)
#pragma unroll
            for (int nt = 0; nt < 8; nt++)
#pragma unroll
                for (int q = 0; q < 4; q++) acc[mt][nt][q] = 0.f;
        gemm128h(EA0, EA1, WB3, acc);
        __syncthreads();  // (D) E2 reads done -> next fill may overwrite

        // epilogue: out[b,i,j0+row] += sum_n ReLU(Z3 + bc3) * Wo  (RED.GLOBAL)
        float* orow = out + ((size_t)b * NNODE + i) * NNODE + j0;
#pragma unroll
        for (int mt = 0; mt < 2; mt++) {
            float s0e = 0.f, s1e = 0.f;
#pragma unroll
            for (int nt = 0; nt < 8; nt++) {
                int n = n_base + nt * 8 + 2 * tq;
                s0e += fmaxf(acc[mt][nt][0] + bc3s[n], 0.f) * wos[n]
                     + fmaxf(acc[mt][nt][1] + bc3s[n + 1], 0.f) * wos[n + 1];
                s1e += fmaxf(acc[mt][nt][2] + bc3s[n], 0.f) * wos[n]
                     + fmaxf(acc[mt][nt][3] + bc3s[n + 1], 0.f) * wos[n + 1];
            }
            s0e += __shfl_xor_sync(0xffffffffu, s0e, 1);
            s0e += __shfl_xor_sync(0xffffffffu, s0e, 2);
            s1e += __shfl_xor_sync(0xffffffffu, s1e, 1);
            s1e += __shfl_xor_sync(0xffffffffu, s1e, 2);
            if (tq == 0) {
                atomicAdd(orow + m_base + mt * 16 + qid, s0e);
                atomicAdd(orow + m_base + mt * 16 + qid + 8, s1e);
            }
        }
    }
}

// ---------------------------------------------------------------------------
extern "C" void kernel_launch(void* const* d_in, const int* in_sizes, int n_in,
                              void* d_out, int out_size) {
    const float* x   = (const float*)d_in[0];
    const float* Wa  = (const float*)d_in[1];
    const float* ba  = (const float*)d_in[2];
    const float* Wb  = (const float*)d_in[3];
    const float* bb  = (const float*)d_in[4];
    const float* Wc1 = (const float*)d_in[5];
    const float* bc1 = (const float*)d_in[6];
    const float* Wc2 = (const float*)d_in[7];
    const float* bc2 = (const float*)d_in[8];
    const float* Wc3 = (const float*)d_in[9];
    const float* bc3 = (const float*)d_in[10];
    const float* Wo  = (const float*)d_in[11];
    const float* bo  = (const float*)d_in[12];
    float* out = (float*)d_out;

    cudaFuncSetAttribute(stage2_kernel,
                         cudaFuncAttributeMaxDynamicSharedMemorySize, SMEM_BYTES);

    init_out_kernel<<<256, 256>>>(out, bo);
    stage1_kernel<<<(BATCH * NNODE) / S1_NODES, 128>>>(x, Wa, ba, Wb, bb, Wc1);

    int ntiles = BATCH * NNODE * (NNODE / 128);  // 4096
    stage2_kernel<<<304, 256, SMEM_BYTES>>>(bc1, Wc2, bc2, Wc3, bc3, Wo,
                                            out, ntiles);
}

// round 11
// speedup vs baseline: 1.5495x; 1.5495x over previous
// NOTE (pitfall, R4): harness PTX target is sm_103 (no 'a') -> no tcgen05/TMEM.
// NOTE (pitfall, R3/R6/R8): any restructuring of the GEMM fragment loads
// (ldmatrix, pipelined ldmatrix, LDS.64 uint2) LOSES. The plain scalar-LDS
// inner loop below is the validated optimum — do not touch it.
#include <cuda_runtime.h>
#include <cuda_fp16.h>
#include <stdint.h>

#define H     128
#define CIN   64
#define NNODE 512
#define BATCH 2

// uint32 (=half2) strides, conflict-free per-fragment (validated R2/R5)
#define ESTRIDE 68    // E tile: 128 rows x 64 half2
#define WSTRIDE 136   // W tile: 64 kpair-rows x 128 n

// smem layout (bytes)
#define OFF_ES   0
#define SZ_ES    (128 * ESTRIDE * 4)             // 34816
#define OFF_W2   (OFF_ES + SZ_ES)                // 34816
#define SZ_W     (64 * WSTRIDE * 4)              // 34816
#define OFF_W3   (OFF_W2 + SZ_W)                 // 69632
#define OFF_BC2  (OFF_W3 + SZ_W)                 // 104448
#define OFF_BC3  (OFF_BC2 + 512)
#define OFF_WO   (OFF_BC3 + 512)
#define SMEM_BYTES (OFF_WO + 512)                // 105984

// scratch: u[b,n,k] = (relu-MLP h2)[b,n,:] @ Wc1  (fp32 + fp16 copies)
__device__ float  g_U [BATCH * NNODE * H];
__device__ __half g_Uh[BATCH * NNODE * H];

// ---------------------------------------------------------------------------
__device__ __forceinline__ uint32_t pack2(float a, float b) {
    __half2 h = __floats2half2_rn(a, b);
    return *reinterpret_cast<uint32_t*>(&h);
}

// relu(a + b) in packed half2
__device__ __forceinline__ uint32_t h2addrelu(uint32_t a, uint32_t b) {
    __half2 z = __float2half2_rn(0.f);
    __half2 r = __hmax2(__hadd2(*reinterpret_cast<__half2*>(&a),
                                *reinterpret_cast<__half2*>(&b)), z);
    return *reinterpret_cast<uint32_t*>(&r);
}

__device__ __forceinline__ void mma_f16(float c[4], const uint32_t a[4],
                                        uint32_t b0, uint32_t b1) {
    asm("mma.sync.aligned.m16n8k16.row.col.f32.f16.f16.f32 "
        "{%0,%1,%2,%3}, {%4,%5,%6,%7}, {%8,%9}, {%0,%1,%2,%3};"
        : "+f"(c[0]), "+f"(c[1]), "+f"(c[2]), "+f"(c[3])
        : "r"(a[0]), "r"(a[1]), "r"(a[2]), "r"(a[3]), "r"(b0), "r"(b1));
}

// 128x128x128 fp16 GEMM: acc += Es(128x128 half) @ Ws(128x128 half)
// DO NOT MODIFY (see pitfall note at top).
__device__ __forceinline__ void gemm128h(const uint32_t* __restrict__ Es,
                                         const uint32_t* __restrict__ Ws,
                                         float acc[2][8][4],
                                         int m_base, int n_base, int qid, int tq) {
#pragma unroll
    for (int k0 = 0; k0 < 64; k0 += 8) {   // k0 in half2 units (16 halves/step)
        uint32_t a[2][4];
#pragma unroll
        for (int mt = 0; mt < 2; mt++) {
            const uint32_t* er = Es + (m_base + mt * 16 + qid) * ESTRIDE + k0 + tq;
            a[mt][0] = er[0];
            a[mt][1] = er[8 * ESTRIDE];
            a[mt][2] = er[4];
            a[mt][3] = er[8 * ESTRIDE + 4];
        }
        const uint32_t* wr = Ws + (k0 + tq) * WSTRIDE + n_base + qid;
#pragma unroll
        for (int nt = 0; nt < 8; nt++) {
            uint32_t b0 = wr[nt * 8];
            uint32_t b1 = wr[4 * WSTRIDE + nt * 8];
            mma_f16(acc[0][nt], a[0], b0, b1);
            mma_f16(acc[1][nt], a[1], b0, b1);
        }
    }
}

// ---------------------------------------------------------------------------
// stage 1: node MLP + u = h2 @ Wc1 (fp32 exact) + out=bo init (folded launch)
// ---------------------------------------------------------------------------
#define S1_NODES 4
__global__ __launch_bounds__(128) void stage1_kernel(
    const float* __restrict__ x,
    const float* __restrict__ Wa, const float* __restrict__ ba,
    const float* __restrict__ Wb, const float* __restrict__ bb,
    const float* __restrict__ Wc1,
    float* __restrict__ out, const float* __restrict__ bo) {
    __shared__ float xs[S1_NODES][CIN];
    __shared__ float h1s[S1_NODES][H + 4];
    __shared__ float h2s[S1_NODES][H + 4];
    int tid = threadIdx.x;
    int node0 = blockIdx.x * S1_NODES;

    // folded init: 32768 threads x 16 floats = 524288 = out_size
    {
        float v = bo[0];
        float4 vv = make_float4(v, v, v, v);
        float4* o4 = (float4*)out + (size_t)(blockIdx.x * 128 + tid) * 4;
        o4[0] = vv; o4[1] = vv; o4[2] = vv; o4[3] = vv;
    }

    for (int idx = tid; idx < S1_NODES * CIN; idx += 128)
        xs[idx / CIN][idx % CIN] = x[node0 * CIN + idx];
    __syncthreads();

    int k = tid;
    float acc[S1_NODES];
#pragma unroll
    for (int m = 0; m < S1_NODES; m++) acc[m] = ba[k];
#pragma unroll 8
    for (int c = 0; c < CIN; c++) {
        float w = Wa[c * H + k];
#pragma unroll
        for (int m = 0; m < S1_NODES; m++) acc[m] += xs[m][c] * w;
    }
#pragma unroll
    for (int m = 0; m < S1_NODES; m++) h1s[m][k] = fmaxf(acc[m], 0.f);
    __syncthreads();

#pragma unroll
    for (int m = 0; m < S1_NODES; m++) acc[m] = bb[k];
#pragma unroll 8
    for (int c = 0; c < H; c++) {
        float w = Wb[c * H + k];
#pragma unroll
        for (int m = 0; m < S1_NODES; m++) acc[m] += h1s[m][c] * w;
    }
#pragma unroll
    for (int m = 0; m < S1_NODES; m++) h2s[m][k] = fmaxf(acc[m], 0.f);
    __syncthreads();

#pragma unroll
    for (int m = 0; m < S1_NODES; m++) acc[m] = 0.f;
#pragma unroll 8
    for (int c = 0; c < H; c++) {
        float w = Wc1[c * H + k];
#pragma unroll
        for (int m = 0; m < S1_NODES; m++) acc[m] += h2s[m][c] * w;
    }
#pragma unroll
    for (int m = 0; m < S1_NODES; m++) {
        g_U [(node0 + m) * H + k] = acc[m];
        g_Uh[(node0 + m) * H + k] = __float2half(acc[m]);
    }
}

// ---------------------------------------------------------------------------
// stage 2: per-edge MLP via fp16 mma (fp32 accum), 2 CTAs / SM, 4 syncs/tile
// fill reads fp16 U (half the bytes/instrs of R5); GEMM identical to R5.
// ---------------------------------------------------------------------------
__global__ __launch_bounds__(256, 2) void stage2_kernel(
    const float* __restrict__ bc1,
    const float* __restrict__ Wc2, const float* __restrict__ bc2,
    const float* __restrict__ Wc3, const float* __restrict__ bc3,
    const float* __restrict__ Wo,
    float* __restrict__ out, int ntiles) {
    extern __shared__ unsigned char smem[];
    uint32_t* Es  = (uint32_t*)(smem + OFF_ES);
    uint32_t* W2s = (uint32_t*)(smem + OFF_W2);
    uint32_t* W3s = (uint32_t*)(smem + OFF_W3);
    float* bc2s = (float*)(smem + OFF_BC2);
    float* bc3s = (float*)(smem + OFF_BC3);
    float* wos  = (float*)(smem + OFF_WO);

    int tid = threadIdx.x;

    // one-time: stage weights as half2 (k-pair packed)
    for (int idx = tid; idx < 64 * H; idx += 256) {
        int kp = idx >> 7, n = idx & 127;
        W2s[kp * WSTRIDE + n] = pack2(Wc2[(2 * kp) * H + n], Wc2[(2 * kp + 1) * H + n]);
        W3s[kp * WSTRIDE + n] = pack2(Wc3[(2 * kp) * H + n], Wc3[(2 * kp + 1) * H + n]);
    }
    if (tid < H) {
        bc2s[tid] = bc2[tid];
        bc3s[tid] = bc3[tid];
        wos[tid]  = Wo[tid];
    }

    // fill mapping: thread owns 8 halves (cols cg*8..cg*8+7), 8 rows (rph+16it)
    int cg  = tid & 15;
    int rph = tid >> 4;
    float4 b0f = ((const float4*)bc1)[cg * 2];
    float4 b1f = ((const float4*)bc1)[cg * 2 + 1];
    __syncthreads();

    int warp = tid >> 5, lane = tid & 31;
    int wm = warp >> 1, wn = warp & 1;
    int m_base = wm * 32, n_base = wn * 64;
    int qid = lane >> 2, tq = lane & 3;

    for (int t = blockIdx.x; t < ntiles; t += gridDim.x) {
        int jt = t & 3;
        int i  = (t >> 2) & (NNODE - 1);
        int b  = t >> 11;
        int j0 = jt << 7;

        // vcomb = bc1 - u_i (fp32, this thread's 8 cols) -> 4 half2
        const float4* Ui4 = (const float4*)(g_U + ((size_t)b * NNODE + i) * H + cg * 8);
        float4 u0 = Ui4[0], u1 = Ui4[1];
        uint32_t vc0 = pack2(b0f.x - u0.x, b0f.y - u0.y);
        uint32_t vc1 = pack2(b0f.z - u0.z, b0f.w - u0.w);
        uint32_t vc2 = pack2(b1f.x - u1.x, b1f.y - u1.y);
        uint32_t vc3 = pack2(b1f.z - u1.z, b1f.w - u1.w);

        // E1[j,k] = ReLU(u_j(h) + vc) in half2; 8 rows x 8 halves per thread
        const __half* Uj = g_Uh + ((size_t)b * NNODE + j0) * H + cg * 8;
#pragma unroll
        for (int it = 0; it < 8; it++) {
            int jj = rph + 16 * it;
            uint4 uh = *(const uint4*)(Uj + (size_t)jj * H);
            uint4 e;
            e.x = h2addrelu(uh.x, vc0);
            e.y = h2addrelu(uh.y, vc1);
            e.z = h2addrelu(uh.z, vc2);
            e.w = h2addrelu(uh.w, vc3);
            *(uint4*)(Es + jj * ESTRIDE + cg * 4) = e;
        }
        __syncthreads();  // (A) E1 ready

        // GEMM1: Z2 = E1 @ Wc2
        float acc[2][8][4];
#pragma unroll
        for (int mt = 0; mt < 2; mt++)
#pragma unroll
            for (int nt = 0; nt < 8; nt++)
#pragma unroll
                for (int q = 0; q < 4; q++) acc[mt][nt][q] = 0.f;
        gemm128h(Es, W2s, acc, m_base, n_base, qid, tq);
        __syncthreads();  // (B) E1 reads done

        // E2 = ReLU(Z2 + bc2) -> half2 back into Es
#pragma unroll
        for (int mt = 0; mt < 2; mt++) {
            int r = m_base + mt * 16 + qid;
#pragma unroll
            for (int nt = 0; nt < 8; nt++) {
                int n  = n_base + nt * 8 + 2 * tq;
                int np = n >> 1;
                Es[r * ESTRIDE + np] =
                    pack2(fmaxf(acc[mt][nt][0] + bc2s[n], 0.f),
                          fmaxf(acc[mt][nt][1] + bc2s[n + 1], 0.f));
                Es[(r + 8) * ESTRIDE + np] =
                    pack2(fmaxf(acc[mt][nt][2] + bc2s[n], 0.f),
                          fmaxf(acc[mt][nt][3] + bc2s[n + 1], 0.f));
            }
        }
        __syncthreads();  // (C) E2 ready

        // GEMM2: Z3 = E2 @ Wc3
#pragma unroll
        for (int mt = 0; mt < 2; mt++)
#pragma unroll
            for (int nt = 0; nt < 8; nt++)
#pragma unroll
                for (int q = 0; q < 4; q++) acc[mt][nt][q] = 0.f;
        gemm128h(Es, W3s, acc, m_base, n_base, qid, tq);
        __syncthreads();  // (D) E2 reads done -> next fill may overwrite

        // epilogue: out[b,i,j0+row] += sum_n ReLU(Z3 + bc3) * Wo  (RED.GLOBAL)
        float* orow = out + ((size_t)b * NNODE + i) * NNODE + j0;
#pragma unroll
        for (int mt = 0; mt < 2; mt++) {
            float s0e = 0.f, s1e = 0.f;
#pragma unroll
            for (int nt = 0; nt < 8; nt++) {
                int n = n_base + nt * 8 + 2 * tq;
                s0e += fmaxf(acc[mt][nt][0] + bc3s[n], 0.f) * wos[n]
                     + fmaxf(acc[mt][nt][1] + bc3s[n + 1], 0.f) * wos[n + 1];
                s1e += fmaxf(acc[mt][nt][2] + bc3s[n], 0.f) * wos[n]
                     + fmaxf(acc[mt][nt][3] + bc3s[n + 1], 0.f) * wos[n + 1];
            }
            s0e += __shfl_xor_sync(0xffffffffu, s0e, 1);
            s0e += __shfl_xor_sync(0xffffffffu, s0e, 2);
            s1e += __shfl_xor_sync(0xffffffffu, s1e, 1);
            s1e += __shfl_xor_sync(0xffffffffu, s1e, 2);
            if (tq == 0) {
                atomicAdd(orow + m_base + mt * 16 + qid, s0e);
                atomicAdd(orow + m_base + mt * 16 + qid + 8, s1e);
            }
        }
    }
}

// ---------------------------------------------------------------------------
extern "C" void kernel_launch(void* const* d_in, const int* in_sizes, int n_in,
                              void* d_out, int out_size) {
    const float* x   = (const float*)d_in[0];
    const float* Wa  = (const float*)d_in[1];
    const float* ba  = (const float*)d_in[2];
    const float* Wb  = (const float*)d_in[3];
    const float* bb  = (const float*)d_in[4];
    const float* Wc1 = (const float*)d_in[5];
    const float* bc1 = (const float*)d_in[6];
    const float* Wc2 = (const float*)d_in[7];
    const float* bc2 = (const float*)d_in[8];
    const float* Wc3 = (const float*)d_in[9];
    const float* bc3 = (const float*)d_in[10];
    const float* Wo  = (const float*)d_in[11];
    const float* bo  = (const float*)d_in[12];
    float* out = (float*)d_out;

    cudaFuncSetAttribute(stage2_kernel,
                         cudaFuncAttributeMaxDynamicSharedMemorySize, SMEM_BYTES);

    stage1_kernel<<<(BATCH * NNODE) / S1_NODES, 128>>>(x, Wa, ba, Wb, bb, Wc1,
                                                       out, bo);

    int ntiles = BATCH * NNODE * (NNODE / 128);  // 4096
    stage2_kernel<<<304, 256, SMEM_BYTES>>>(bc1, Wc2, bc2, Wc3, bc3, Wo,
                                            out, ntiles);
}